// round 9
// baseline (speedup 1.0000x reference)
#include <cuda_runtime.h>
#include <cstdint>
#include <math.h>

// SimRel via single-pass fp16 mma.sync. R9: 512 threads (16 warps) x 2 CTAs/SM
// = 50% occupancy to close the latency-exposure gap seen at R8 (no pipe >55%,
// wall ~1.8x the binding resource). Tile M=128, warp tiles 32x16 (4Mx4N slots),
// each warp converts 8 rows (one wave, 64 prefetch regs), single X smem buffer,
// streaming LDG/STG. out = dot * rsqrt(|x|^2) * rsqrt(|a|^2); 1.0 on inf rows.
// B=262144, D=256, C=64.

#define THREADS 512
#define SROW    528                 // 264 fp16 per row (256 + 8 pad), bytes

// ---- smem layout (bytes) ----
#define S_A     0                   // [64 x 264] fp16 centroids     33792
#define S_X     33792               // [128 x 264] fp16 X tile       67584
#define S_XINV  101376              // [128] f32 row rsqrt norms       512
#define S_CNI   101888              // [64] f32 centroid rsqrt norms   256
#define S_INF   102144              // [64] int inf flags              256
#define S_TOTAL 102400

__device__ __forceinline__ void sts64(uint32_t a, uint32_t x, uint32_t y) {
    asm volatile("st.shared.v2.b32 [%0], {%1,%2};" :: "r"(a), "r"(x), "r"(y));
}
__device__ __forceinline__ void ldsm4(uint32_t a, uint32_t& r0, uint32_t& r1,
                                      uint32_t& r2, uint32_t& r3) {
    asm volatile("ldmatrix.sync.aligned.m8n8.x4.shared.b16 {%0,%1,%2,%3}, [%4];"
                 : "=r"(r0), "=r"(r1), "=r"(r2), "=r"(r3) : "r"(a));
}
__device__ __forceinline__ void mma16816(float* c, uint32_t a0, uint32_t a1,
                                         uint32_t a2, uint32_t a3,
                                         uint32_t b0, uint32_t b1) {
    asm volatile("mma.sync.aligned.m16n8k16.row.col.f32.f16.f16.f32 "
                 "{%0,%1,%2,%3}, {%4,%5,%6,%7}, {%8,%9}, {%0,%1,%2,%3};"
                 : "+f"(c[0]), "+f"(c[1]), "+f"(c[2]), "+f"(c[3])
                 : "r"(a0), "r"(a1), "r"(a2), "r"(a3), "r"(b0), "r"(b1));
}
__device__ __forceinline__ void cvt_f16(float4 v, uint32_t& r0, uint32_t& r1) {
    asm("cvt.rn.f16x2.f32 %0, %1, %2;" : "=r"(r0) : "f"(v.y), "f"(v.x));
    asm("cvt.rn.f16x2.f32 %0, %1, %2;" : "=r"(r1) : "f"(v.w), "f"(v.z));
}
__device__ __forceinline__ void stg_cs64(float* p, float2 v) {
    asm volatile("st.global.cs.v2.f32 [%0], {%1,%2};" :: "l"(p), "f"(v.x), "f"(v.y));
}
__device__ __forceinline__ float sum8(float4 a, float4 b) {
    float s = a.x * a.x;
    s = fmaf(a.y, a.y, s); s = fmaf(a.z, a.z, s); s = fmaf(a.w, a.w, s);
    s = fmaf(b.x, b.x, s); s = fmaf(b.y, b.y, s);
    s = fmaf(b.z, b.z, s); s = fmaf(b.w, b.w, s);
    return s;
}

__global__ void __launch_bounds__(THREADS, 2)
SimRel_48335561949951_kernel(const float* __restrict__ X,
                             const float* __restrict__ A,
                             float* __restrict__ out,
                             int B, int ntiles) {
    extern __shared__ char smem[];
    const uint32_t sb = (uint32_t)__cvta_generic_to_shared(smem);
    float* xinv_s = (float*)(smem + S_XINV);
    float* cni_s  = (float*)(smem + S_CNI);
    int*   inf_s  = (int*)(smem + S_INF);

    const int tid = threadIdx.x, w = tid >> 5, l = tid & 31;
    const int q = w >> 2;           // M-slot: rows q*32..q*32+31
    const int h = w & 3;            // N-slot: classes h*16..h*16+15

    // ---- centroid conversion + norms + inf flags (4 rows per warp, once) ----
    #pragma unroll
    for (int rr = 0; rr < 4; rr++) {
        int r = w * 4 + rr;
        const float4* pa = (const float4*)(A + (size_t)r * 256);
        float4 v0 = pa[l], v1 = pa[32 + l];
        uint32_t c0r, c1r;
        cvt_f16(v0, c0r, c1r);
        sts64(sb + S_A + r * SROW + 8 * l, c0r, c1r);
        cvt_f16(v1, c0r, c1r);
        sts64(sb + S_A + r * SROW + 256 + 8 * l, c0r, c1r);
        float ss = sum8(v0, v1);
        int bad = (fabsf(v0.x) == INFINITY) | (fabsf(v0.y) == INFINITY) |
                  (fabsf(v0.z) == INFINITY) | (fabsf(v0.w) == INFINITY) |
                  (fabsf(v1.x) == INFINITY) | (fabsf(v1.y) == INFINITY) |
                  (fabsf(v1.z) == INFINITY) | (fabsf(v1.w) == INFINITY);
        #pragma unroll
        for (int o = 16; o; o >>= 1) ss += __shfl_xor_sync(0xffffffffu, ss, o);
        unsigned m = __ballot_sync(0xffffffffu, bad);
        if (l == 0) { cni_s[r] = rsqrtf(ss); inf_s[r] = (m != 0); }
    }
    __syncthreads();

    // ---- per-lane ldmatrix fragment offsets ----
    const int t8 = l >> 3;
    const uint32_t frag_off = (uint32_t)(((t8 & 1) * 8 + (l & 7)) * SROW + (t8 >> 1) * 16);
    const uint32_t xf0 = sb + S_X + (uint32_t)(q * 32) * SROW + frag_off;   // m-group 0
    const uint32_t xf1 = xf0 + 16 * SROW;                                    // m-group 1
    const uint32_t af  = sb + S_A + (uint32_t)(h * 16) * SROW + frag_off;   // 16 classes

    const int rbase = w * 8;        // 8 rows this warp loads/converts
    const int qr = l >> 2, qc = (l & 3) * 2;

    // ---- prologue: prefetch first tile's 8 rows into registers ----
    float4 va[8], vb[8];
    {
        long long tb = (long long)blockIdx.x * 128;
        #pragma unroll
        for (int rr = 0; rr < 8; rr++) {
            long long gr = tb + rbase + rr; if (gr >= B) gr = B - 1;
            const float4* px = (const float4*)(X + gr * 256);
            va[rr] = __ldcs(px + l);
            vb[rr] = __ldcs(px + 32 + l);
        }
    }

    for (int tile = blockIdx.x; tile < ntiles; tile += gridDim.x) {
        const long long tb = (long long)tile * 128;

        // phase 1: convert prefetched rows -> fp16 smem + fp32 row norms
        {
            const uint32_t xsh = sb + S_X + (uint32_t)rbase * SROW;
            #pragma unroll
            for (int rr = 0; rr < 8; rr++) {
                uint32_t c0r, c1r;
                cvt_f16(va[rr], c0r, c1r);
                sts64(xsh + rr * SROW + 8 * l, c0r, c1r);
                cvt_f16(vb[rr], c0r, c1r);
                sts64(xsh + rr * SROW + 256 + 8 * l, c0r, c1r);
                float ss = sum8(va[rr], vb[rr]);
                #pragma unroll
                for (int o = 16; o; o >>= 1) ss += __shfl_xor_sync(0xffffffffu, ss, o);
                if (l == 0) xinv_s[rbase + rr] = rsqrtf(ss);
            }
        }
        __syncthreads();   // X tile + norms complete; MMA(t-1) reads done

        // phase 2a: issue next tile's LDGs (latency covered by MMA below)
        int nt = tile + gridDim.x;
        if (nt < ntiles) {
            long long nb = (long long)nt * 128;
            #pragma unroll
            for (int rr = 0; rr < 8; rr++) {
                long long gr = nb + rbase + rr; if (gr >= B) gr = B - 1;
                const float4* px = (const float4*)(X + gr * 256);
                va[rr] = __ldcs(px + l);
                vb[rr] = __ldcs(px + 32 + l);
            }
        }

        // phase 2b: 16 k-steps; warp computes 32 rows x 16 classes
        float acc[2][2][4];
        #pragma unroll
        for (int m = 0; m < 2; m++)
            #pragma unroll
            for (int n = 0; n < 2; n++)
                #pragma unroll
                for (int j = 0; j < 4; j++) acc[m][n][j] = 0.0f;

        #pragma unroll
        for (int s = 0; s < 16; s++) {
            uint32_t x0[4], x1[4], b0, b1, b2, b3;
            ldsm4(xf0 + s * 32, x0[0], x0[1], x0[2], x0[3]);
            ldsm4(xf1 + s * 32, x1[0], x1[1], x1[2], x1[3]);
            ldsm4(af + s * 32, b0, b1, b2, b3);
            mma16816(acc[0][0], x0[0], x0[1], x0[2], x0[3], b0, b2);
            mma16816(acc[0][1], x0[0], x0[1], x0[2], x0[3], b1, b3);
            mma16816(acc[1][0], x1[0], x1[1], x1[2], x1[3], b0, b2);
            mma16816(acc[1][1], x1[0], x1[1], x1[2], x1[3], b1, b3);
        }

        // phase 3: epilogue — scale + streaming store (32 rows x 16 classes)
        #pragma unroll
        for (int m = 0; m < 2; m++) {
            int rloc = q * 32 + m * 16 + qr;
            float xi0 = xinv_s[rloc];
            float xi1 = xinv_s[rloc + 8];
            long long r0g = tb + rloc;
            float* o0 = out + r0g * 64;
            float* o1 = o0 + 8 * 64;
            #pragma unroll
            for (int n = 0; n < 2; n++) {
                int c0 = h * 16 + n * 8 + qc;
                float2 cn2 = *(const float2*)(cni_s + c0);
                int2   ff  = *(const int2*)(inf_s + c0);
                float2 s0, s1;
                s0.x = ff.x ? 1.0f : acc[m][n][0] * xi0 * cn2.x;
                s0.y = ff.y ? 1.0f : acc[m][n][1] * xi0 * cn2.y;
                s1.x = ff.x ? 1.0f : acc[m][n][2] * xi1 * cn2.x;
                s1.y = ff.y ? 1.0f : acc[m][n][3] * xi1 * cn2.y;
                if (r0g < B)     stg_cs64(o0 + c0, s0);
                if (r0g + 8 < B) stg_cs64(o1 + c0, s1);
            }
        }
        __syncthreads();   // all ldsm reads done before next tile's STS (WAR)
    }
}

extern "C" void kernel_launch(void* const* d_in, const int* in_sizes, int n_in,
                              void* d_out, int out_size) {
    const float* X = (const float*)d_in[0];   // inputs [B, 256] fp32
    // d_in[1] = labels (unused)
    const float* A = (const float*)d_in[2];   // class_avgs [64, 256] fp32
    float* out = (float*)d_out;

    int B = in_sizes[0] / 256;
    int ntiles = (B + 127) / 128;

    int dev = 0, nsm = 148;
    cudaGetDevice(&dev);
    cudaDeviceGetAttribute(&nsm, cudaDevAttrMultiProcessorCount, dev);

    int grid = 2 * nsm;             // 2 CTAs/SM, 32 warps/SM
    if (grid > ntiles) grid = ntiles;

    cudaFuncSetAttribute(SimRel_48335561949951_kernel,
                         cudaFuncAttributeMaxDynamicSharedMemorySize, S_TOTAL);

    SimRel_48335561949951_kernel<<<grid, THREADS, S_TOTAL>>>(X, A, out, B, ntiles);
}

// round 10
// speedup vs baseline: 1.4726x; 1.4726x over previous
#include <cuda_runtime.h>
#include <cstdint>
#include <math.h>

// SimRel via single-pass fp16 mma.sync. R10: 256 thr x 3 CTAs/SM (24 warps/SM,
// reg cap 85 — no spill, unlike R9's 512thr/64reg trap). Tile M=64, warp tile
// 16 rows x 32 classes, 4-row LDG waves (wave1 issued before wave0 convert;
// next tile's wave0 prefetched across MMA). Streaming LDG/STG.
// out = dot * rsqrt(|x|^2) * rsqrt(|a|^2) (norms exact fp32); 1.0 on inf rows.
// B=262144, D=256, C=64.

#define THREADS 256
#define SROW    528                 // 264 fp16 per row (256 + 8 pad), bytes

// ---- smem layout (bytes) ----
#define S_A     0                   // [64 x 264] fp16 centroids     33792
#define S_X     33792               // [64 x 264] fp16 X tile        33792
#define S_XINV  67584               // [64] f32 row rsqrt norms        256
#define S_CNI   67840               // [64] f32 centroid rsqrt norms   256
#define S_INF   68096               // [64] int inf flags              256
#define S_TOTAL 68352               // x3 CTAs = 205KB <= 228KB/SM

__device__ __forceinline__ void sts64(uint32_t a, uint32_t x, uint32_t y) {
    asm volatile("st.shared.v2.b32 [%0], {%1,%2};" :: "r"(a), "r"(x), "r"(y));
}
__device__ __forceinline__ void ldsm4(uint32_t a, uint32_t& r0, uint32_t& r1,
                                      uint32_t& r2, uint32_t& r3) {
    asm volatile("ldmatrix.sync.aligned.m8n8.x4.shared.b16 {%0,%1,%2,%3}, [%4];"
                 : "=r"(r0), "=r"(r1), "=r"(r2), "=r"(r3) : "r"(a));
}
__device__ __forceinline__ void mma16816(float* c, uint32_t a0, uint32_t a1,
                                         uint32_t a2, uint32_t a3,
                                         uint32_t b0, uint32_t b1) {
    asm volatile("mma.sync.aligned.m16n8k16.row.col.f32.f16.f16.f32 "
                 "{%0,%1,%2,%3}, {%4,%5,%6,%7}, {%8,%9}, {%0,%1,%2,%3};"
                 : "+f"(c[0]), "+f"(c[1]), "+f"(c[2]), "+f"(c[3])
                 : "r"(a0), "r"(a1), "r"(a2), "r"(a3), "r"(b0), "r"(b1));
}
__device__ __forceinline__ void cvt_f16(float4 v, uint32_t& r0, uint32_t& r1) {
    asm("cvt.rn.f16x2.f32 %0, %1, %2;" : "=r"(r0) : "f"(v.y), "f"(v.x));
    asm("cvt.rn.f16x2.f32 %0, %1, %2;" : "=r"(r1) : "f"(v.w), "f"(v.z));
}
__device__ __forceinline__ void stg_cs64(float* p, float2 v) {
    asm volatile("st.global.cs.v2.f32 [%0], {%1,%2};" :: "l"(p), "f"(v.x), "f"(v.y));
}
__device__ __forceinline__ float sum8(float4 a, float4 b) {
    float s = a.x * a.x;
    s = fmaf(a.y, a.y, s); s = fmaf(a.z, a.z, s); s = fmaf(a.w, a.w, s);
    s = fmaf(b.x, b.x, s); s = fmaf(b.y, b.y, s);
    s = fmaf(b.z, b.z, s); s = fmaf(b.w, b.w, s);
    return s;
}

__global__ void __launch_bounds__(THREADS, 3)
SimRel_48335561949951_kernel(const float* __restrict__ X,
                             const float* __restrict__ A,
                             float* __restrict__ out,
                             int B, int ntiles) {
    extern __shared__ char smem[];
    const uint32_t sb = (uint32_t)__cvta_generic_to_shared(smem);
    float* xinv_s = (float*)(smem + S_XINV);
    float* cni_s  = (float*)(smem + S_CNI);
    int*   inf_s  = (int*)(smem + S_INF);

    const int tid = threadIdx.x, w = tid >> 5, l = tid & 31;
    const int q = w >> 1;           // M-slot: rows q*16..q*16+15
    const int h = w & 1;            // N-slot: classes h*32..h*32+31

    // ---- centroid conversion + norms + inf flags (8 rows per warp, once) ----
    #pragma unroll
    for (int rr = 0; rr < 8; rr++) {
        int r = w * 8 + rr;
        const float4* pa = (const float4*)(A + (size_t)r * 256);
        float4 v0 = pa[l], v1 = pa[32 + l];
        uint32_t c0r, c1r;
        cvt_f16(v0, c0r, c1r);
        sts64(sb + S_A + r * SROW + 8 * l, c0r, c1r);
        cvt_f16(v1, c0r, c1r);
        sts64(sb + S_A + r * SROW + 256 + 8 * l, c0r, c1r);
        float ss = sum8(v0, v1);
        int bad = (fabsf(v0.x) == INFINITY) | (fabsf(v0.y) == INFINITY) |
                  (fabsf(v0.z) == INFINITY) | (fabsf(v0.w) == INFINITY) |
                  (fabsf(v1.x) == INFINITY) | (fabsf(v1.y) == INFINITY) |
                  (fabsf(v1.z) == INFINITY) | (fabsf(v1.w) == INFINITY);
        #pragma unroll
        for (int o = 16; o; o >>= 1) ss += __shfl_xor_sync(0xffffffffu, ss, o);
        unsigned m = __ballot_sync(0xffffffffu, bad);
        if (l == 0) { cni_s[r] = rsqrtf(ss); inf_s[r] = (m != 0); }
    }
    __syncthreads();

    // ---- per-lane ldmatrix fragment offsets ----
    const int t8 = l >> 3;
    const uint32_t frag_off = (uint32_t)(((t8 & 1) * 8 + (l & 7)) * SROW + (t8 >> 1) * 16);
    const uint32_t xf  = sb + S_X + (uint32_t)(q * 16) * SROW + frag_off;   // 16 rows
    const uint32_t af0 = sb + S_A + (uint32_t)(h * 32) * SROW + frag_off;   // cls +0..15
    const uint32_t af1 = af0 + 16 * SROW;                                    // cls +16..31

    const int rbase = w * 8;        // 8 rows this warp loads (2 waves of 4)
    const int qr = l >> 2, qc = (l & 3) * 2;

    // ---- prologue: LDG wave0 (rows rbase..rbase+3) of first tile ----
    float4 p0[4], p1[4];            // wave0: k 0-127 / k 128-255
    {
        long long tb = (long long)blockIdx.x * 64;
        #pragma unroll
        for (int rr = 0; rr < 4; rr++) {
            long long gr = tb + rbase + rr; if (gr >= B) gr = B - 1;
            const float4* px = (const float4*)(X + gr * 256);
            p0[rr] = __ldcs(px + l);
            p1[rr] = __ldcs(px + 32 + l);
        }
    }

    for (int tile = blockIdx.x; tile < ntiles; tile += gridDim.x) {
        const long long tb = (long long)tile * 64;
        const uint32_t xsh = sb + S_X + (uint32_t)rbase * SROW;

        // LDG wave1 first (rows rbase+4..+7) so its latency is covered by
        // wave0's convert below. (acc regs are dead here -> 64 live regs OK.)
        float4 s0[4], s1[4];
        #pragma unroll
        for (int rr = 0; rr < 4; rr++) {
            long long gr = tb + rbase + 4 + rr; if (gr >= B) gr = B - 1;
            const float4* px = (const float4*)(X + gr * 256);
            s0[rr] = __ldcs(px + l);
            s1[rr] = __ldcs(px + 32 + l);
        }

        // convert wave0 -> fp16 smem + norms
        #pragma unroll
        for (int rr = 0; rr < 4; rr++) {
            uint32_t c0r, c1r;
            cvt_f16(p0[rr], c0r, c1r);
            sts64(xsh + rr * SROW + 8 * l, c0r, c1r);
            cvt_f16(p1[rr], c0r, c1r);
            sts64(xsh + rr * SROW + 256 + 8 * l, c0r, c1r);
            float ss = sum8(p0[rr], p1[rr]);
            #pragma unroll
            for (int o = 16; o; o >>= 1) ss += __shfl_xor_sync(0xffffffffu, ss, o);
            if (l == 0) xinv_s[rbase + rr] = rsqrtf(ss);
        }
        // convert wave1
        #pragma unroll
        for (int rr = 0; rr < 4; rr++) {
            uint32_t c0r, c1r;
            cvt_f16(s0[rr], c0r, c1r);
            sts64(xsh + (4 + rr) * SROW + 8 * l, c0r, c1r);
            cvt_f16(s1[rr], c0r, c1r);
            sts64(xsh + (4 + rr) * SROW + 256 + 8 * l, c0r, c1r);
            float ss = sum8(s0[rr], s1[rr]);
            #pragma unroll
            for (int o = 16; o; o >>= 1) ss += __shfl_xor_sync(0xffffffffu, ss, o);
            if (l == 0) xinv_s[rbase + 4 + rr] = rsqrtf(ss);
        }
        __syncthreads();   // X tile + norms complete; MMA(t-1) reads done

        // prefetch wave0 of next tile (latency covered by MMA below)
        int nt = tile + gridDim.x;
        if (nt < ntiles) {
            long long nb = (long long)nt * 64;
            #pragma unroll
            for (int rr = 0; rr < 4; rr++) {
                long long gr = nb + rbase + rr; if (gr >= B) gr = B - 1;
                const float4* px = (const float4*)(X + gr * 256);
                p0[rr] = __ldcs(px + l);
                p1[rr] = __ldcs(px + 32 + l);
            }
        }

        // MMA: 16 k-steps; warp computes 16 rows x 32 classes
        float acc[4][4];
        #pragma unroll
        for (int n = 0; n < 4; n++)
            #pragma unroll
            for (int j = 0; j < 4; j++) acc[n][j] = 0.0f;

        #pragma unroll
        for (int s = 0; s < 16; s++) {
            uint32_t a0, a1, a2, a3, b0, b1, b2, b3, c0, c1, c2, c3;
            ldsm4(xf + s * 32, a0, a1, a2, a3);
            ldsm4(af0 + s * 32, b0, b1, b2, b3);
            ldsm4(af1 + s * 32, c0, c1, c2, c3);
            mma16816(acc[0], a0, a1, a2, a3, b0, b2);
            mma16816(acc[1], a0, a1, a2, a3, b1, b3);
            mma16816(acc[2], a0, a1, a2, a3, c0, c2);
            mma16816(acc[3], a0, a1, a2, a3, c1, c3);
        }

        // epilogue — scale + streaming store (16 rows x 32 classes per warp)
        {
            int rloc = q * 16 + qr;
            float xi0 = xinv_s[rloc];
            float xi1 = xinv_s[rloc + 8];
            long long r0g = tb + rloc;
            float* o0 = out + r0g * 64;
            float* o1 = o0 + 8 * 64;
            #pragma unroll
            for (int n = 0; n < 4; n++) {
                int c0 = h * 32 + n * 8 + qc;
                float2 cn2 = *(const float2*)(cni_s + c0);
                int2   ff  = *(const int2*)(inf_s + c0);
                float2 v0, v1;
                v0.x = ff.x ? 1.0f : acc[n][0] * xi0 * cn2.x;
                v0.y = ff.y ? 1.0f : acc[n][1] * xi0 * cn2.y;
                v1.x = ff.x ? 1.0f : acc[n][2] * xi1 * cn2.x;
                v1.y = ff.y ? 1.0f : acc[n][3] * xi1 * cn2.y;
                if (r0g < B)     stg_cs64(o0 + c0, v0);
                if (r0g + 8 < B) stg_cs64(o1 + c0, v1);
            }
        }
        __syncthreads();   // all ldsm reads done before next tile's STS (WAR)
    }
}

extern "C" void kernel_launch(void* const* d_in, const int* in_sizes, int n_in,
                              void* d_out, int out_size) {
    const float* X = (const float*)d_in[0];   // inputs [B, 256] fp32
    // d_in[1] = labels (unused)
    const float* A = (const float*)d_in[2];   // class_avgs [64, 256] fp32
    float* out = (float*)d_out;

    int B = in_sizes[0] / 256;
    int ntiles = (B + 63) / 64;

    int dev = 0, nsm = 148;
    cudaGetDevice(&dev);
    cudaDeviceGetAttribute(&nsm, cudaDevAttrMultiProcessorCount, dev);

    int grid = 3 * nsm;             // 3 CTAs/SM, 24 warps/SM
    if (grid > ntiles) grid = ntiles;

    cudaFuncSetAttribute(SimRel_48335561949951_kernel,
                         cudaFuncAttributeMaxDynamicSharedMemorySize, S_TOTAL);

    SimRel_48335561949951_kernel<<<grid, THREADS, S_TOTAL>>>(X, A, out, B, ntiles);
}